// round 1
// baseline (speedup 1.0000x reference)
#include <cuda_runtime.h>

#define NN 384
#define HH 768
#define INV_SQRT_H 0.03608439182435161f   // 1/sqrt(768)

// ---------------- scratch (device globals; no allocation allowed) ----------
__device__ float g_att[NN * NN];          // 576 KB attention logits (pre-scaled)
__device__ float g_rmax[NN], g_rinv[NN];  // row softmax stats (max, 1/sumexp)
__device__ float g_cmax[NN], g_cinv[NN];  // col softmax stats
__device__ float g_hypo_typ[NN], g_hyper_typ[NN];
__device__ float g_w_hypo[NN], g_w_hyper[NN];
__device__ float g_hp[HH], g_xp[HH];      // hyper_prototype, hypo_prototype

// ---------------- helpers ----------------
__device__ __forceinline__ float fast_tanh(float x) {
    float y;
    asm("tanh.approx.f32 %0, %1;" : "=f"(y) : "f"(x));
    return y;
}

__device__ __forceinline__ float block_max128(float v, float* sh) {
    #pragma unroll
    for (int o = 16; o; o >>= 1) v = fmaxf(v, __shfl_xor_sync(0xffffffffu, v, o));
    int w = threadIdx.x >> 5;
    if ((threadIdx.x & 31) == 0) sh[w] = v;
    __syncthreads();
    float r = fmaxf(fmaxf(sh[0], sh[1]), fmaxf(sh[2], sh[3]));
    __syncthreads();
    return r;
}

__device__ __forceinline__ float block_sum128(float v, float* sh) {
    #pragma unroll
    for (int o = 16; o; o >>= 1) v += __shfl_xor_sync(0xffffffffu, v, o);
    int w = threadIdx.x >> 5;
    if ((threadIdx.x & 31) == 0) sh[w] = v;
    __syncthreads();
    float r = (sh[0] + sh[1]) + (sh[2] + sh[3]);
    __syncthreads();
    return r;
}

// ---------------- K1: att[n,m] = invsqrt * sum_h tanh(X[n,h]*Y[m,h]) -------
// 32x32 output tile per block, 16x16 threads, 2x2 micro-tile. MUFU-bound.
__global__ __launch_bounds__(256) void att_kernel(const float* __restrict__ X,
                                                  const float* __restrict__ Y) {
    __shared__ float sX[32][33];
    __shared__ float sY[32][33];
    const int tid = threadIdx.x;
    const int tx = tid & 15;
    const int ty = tid >> 4;
    const int bi = blockIdx.y * 32;  // hypo rows
    const int bj = blockIdx.x * 32;  // hyper rows
    const int lr = tid >> 3;         // 0..31 load row
    const int lk = (tid & 7) << 2;   // 0..28 load k offset

    float a00 = 0.f, a01 = 0.f, a10 = 0.f, a11 = 0.f;

    for (int k0 = 0; k0 < HH; k0 += 32) {
        float4 vx = *(const float4*)(X + (size_t)(bi + lr) * HH + k0 + lk);
        float4 vy = *(const float4*)(Y + (size_t)(bj + lr) * HH + k0 + lk);
        sX[lr][lk + 0] = vx.x; sX[lr][lk + 1] = vx.y;
        sX[lr][lk + 2] = vx.z; sX[lr][lk + 3] = vx.w;
        sY[lr][lk + 0] = vy.x; sY[lr][lk + 1] = vy.y;
        sY[lr][lk + 2] = vy.z; sY[lr][lk + 3] = vy.w;
        __syncthreads();
        #pragma unroll
        for (int k = 0; k < 32; k++) {
            float x0 = sX[2 * ty][k], x1 = sX[2 * ty + 1][k];
            float y0 = sY[2 * tx][k], y1 = sY[2 * tx + 1][k];
            a00 += fast_tanh(x0 * y0);
            a01 += fast_tanh(x0 * y1);
            a10 += fast_tanh(x1 * y0);
            a11 += fast_tanh(x1 * y1);
        }
        __syncthreads();
    }

    const int i = bi + 2 * ty, j = bj + 2 * tx;
    g_att[i * NN + j]           = a00 * INV_SQRT_H;
    g_att[i * NN + j + 1]       = a01 * INV_SQRT_H;
    g_att[(i + 1) * NN + j]     = a10 * INV_SQRT_H;
    g_att[(i + 1) * NN + j + 1] = a11 * INV_SQRT_H;
}

// ---------------- K2: row (b<384) and col (b>=384) softmax stats -----------
__global__ __launch_bounds__(128) void stats_kernel() {
    __shared__ float sh[4];
    const int b = blockIdx.x, t = threadIdx.x;
    float v0, v1, v2;
    if (b < NN) {
        const float* row = g_att + b * NN;
        v0 = row[t]; v1 = row[t + 128]; v2 = row[t + 256];
    } else {
        const int c = b - NN;
        v0 = g_att[t * NN + c];
        v1 = g_att[(t + 128) * NN + c];
        v2 = g_att[(t + 256) * NN + c];
    }
    float m = fmaxf(v0, fmaxf(v1, v2));
    m = block_max128(m, sh);
    float s = __expf(v0 - m) + __expf(v1 - m) + __expf(v2 - m);
    s = block_sum128(s, sh);
    if (t == 0) {
        float inv = 1.0f / s;
        if (b < NN) { g_rmax[b] = m; g_rinv[b] = inv; }
        else        { g_cmax[b - NN] = m; g_cinv[b - NN] = inv; }
    }
}

// ---------------- K3: typicalness vectors -----------------------------------
// hypo_typ[n]  = (1/384) * sum_m Pcol[n,m]   (row pass using col stats)
// hyper_typ[m] = (1/384) * sum_n Prow[n,m]   (col pass using row stats)
__global__ __launch_bounds__(128) void typ_kernel() {
    __shared__ float sh[4];
    const int b = blockIdx.x, t = threadIdx.x;
    float acc = 0.f;
    if (b < NN) {
        const float* row = g_att + b * NN;
        #pragma unroll
        for (int i = 0; i < 3; i++) {
            int m = t + i * 128;
            acc += __expf(row[m] - g_cmax[m]) * g_cinv[m];
        }
        acc = block_sum128(acc, sh);
        if (t == 0) g_hypo_typ[b] = acc * (1.0f / NN);
    } else {
        const int c = b - NN;
        #pragma unroll
        for (int i = 0; i < 3; i++) {
            int n = t + i * 128;
            acc += __expf(g_att[n * NN + c] - g_rmax[n]) * g_rinv[n];
        }
        acc = block_sum128(acc, sh);
        if (t == 0) g_hyper_typ[c] = acc * (1.0f / NN);
    }
}

// ---------------- K4: pooling weight vectors ---------------------------------
// w_hypo[n]  = sum_m Pcol[n,m] * hyper_typ[m]
// w_hyper[m] = sum_n Prow[n,m] * hypo_typ[n]
__global__ __launch_bounds__(128) void wvec_kernel() {
    __shared__ float sh[4];
    const int b = blockIdx.x, t = threadIdx.x;
    float acc = 0.f;
    if (b < NN) {
        const float* row = g_att + b * NN;
        #pragma unroll
        for (int i = 0; i < 3; i++) {
            int m = t + i * 128;
            acc += g_hyper_typ[m] * __expf(row[m] - g_cmax[m]) * g_cinv[m];
        }
        acc = block_sum128(acc, sh);
        if (t == 0) g_w_hypo[b] = acc;
    } else {
        const int c = b - NN;
        #pragma unroll
        for (int i = 0; i < 3; i++) {
            int n = t + i * 128;
            acc += g_hypo_typ[n] * __expf(g_att[n * NN + c] - g_rmax[n]) * g_rinv[n];
        }
        acc = block_sum128(acc, sh);
        if (t == 0) g_w_hyper[c] = acc;
    }
}

// ---------------- K5: prototypes = weighted column sums ---------------------
// g_hp[d] = sum_m w_hyper[m] * Y[m,d];  g_xp[d] = sum_n w_hypo[n] * X[n,d]
__global__ __launch_bounds__(128) void proto_kernel(const float* __restrict__ X,
                                                    const float* __restrict__ Y) {
    __shared__ float wh[NN];
    __shared__ float wx[NN];
    const int t = threadIdx.x;
    #pragma unroll
    for (int i = 0; i < 3; i++) {
        wh[t + i * 128] = g_w_hyper[t + i * 128];
        wx[t + i * 128] = g_w_hypo[t + i * 128];
    }
    __syncthreads();
    const int d = blockIdx.x * 128 + t;
    float hp = 0.f, xp = 0.f;
    #pragma unroll 4
    for (int m = 0; m < NN; m++) {
        hp += wh[m] * Y[(size_t)m * HH + d];
        xp += wx[m] * X[(size_t)m * HH + d];
    }
    g_hp[d] = hp;
    g_xp[d] = xp;
}

// ---------------- K6: feats + classifier -------------------------------------
__global__ __launch_bounds__(128) void cls_kernel(const float* __restrict__ W,
                                                  const float* __restrict__ B,
                                                  float* __restrict__ out) {
    __shared__ float sh[12];
    const int t = threadIdx.x;
    float p0 = 0.f, p1 = 0.f, p2 = 0.f;
    for (int e = t; e < 4 * HH; e += 128) {
        int seg = e / HH;
        int d = e - seg * HH;
        float hp = g_hp[d], xp = g_xp[d];
        float f = (seg == 0) ? hp : (seg == 1) ? xp : (seg == 2) ? (hp - xp) : (hp * xp);
        p0 += W[e] * f;
        p1 += W[4 * HH + e] * f;
        p2 += W[8 * HH + e] * f;
    }
    #pragma unroll
    for (int o = 16; o; o >>= 1) {
        p0 += __shfl_xor_sync(0xffffffffu, p0, o);
        p1 += __shfl_xor_sync(0xffffffffu, p1, o);
        p2 += __shfl_xor_sync(0xffffffffu, p2, o);
    }
    int w = t >> 5;
    if ((t & 31) == 0) { sh[w] = p0; sh[4 + w] = p1; sh[8 + w] = p2; }
    __syncthreads();
    if (t == 0) {
        out[0] = (sh[0] + sh[1]) + (sh[2] + sh[3]) + B[0];
        out[1] = (sh[4] + sh[5]) + (sh[6] + sh[7]) + B[1];
        out[2] = (sh[8] + sh[9]) + (sh[10] + sh[11]) + B[2];
    }
}

// ---------------- launch ------------------------------------------------------
extern "C" void kernel_launch(void* const* d_in, const int* in_sizes, int n_in,
                              void* d_out, int out_size) {
    const float* X = (const float*)d_in[0];  // hypo_embeddings [384,768]
    const float* Y = (const float*)d_in[1];  // hyper_embeddings [384,768]
    const float* W = (const float*)d_in[2];  // W_cls [3,3072]
    const float* B = (const float*)d_in[3];  // b_cls [3]
    float* out = (float*)d_out;              // [3]

    att_kernel<<<dim3(12, 12), 256>>>(X, Y);
    stats_kernel<<<2 * NN, 128>>>();
    typ_kernel<<<2 * NN, 128>>>();
    wvec_kernel<<<2 * NN, 128>>>();
    proto_kernel<<<HH / 128, 128>>>(X, Y);
    cls_kernel<<<1, 128>>>(W, B, out);
}

// round 2
// speedup vs baseline: 1.3491x; 1.3491x over previous
#include <cuda_runtime.h>

#define NN 384
#define HH 768
#define INV_SQRT_H 0.03608439182435161f   // 1/sqrt(768)
#define INV_N      0.0026041666666666665f // 1/384

// ---------------- scratch (device globals; no allocation allowed) ----------
__device__ float g_E [NN * NN];           // exp(att)            576 KB
__device__ float g_ET[NN * NN];           // exp(att) transposed 576 KB
__device__ float g_rinv[NN], g_cinv[NN];  // 1/rowsum(E), 1/colsum(E)
__device__ float g_a[NN], g_b[NN];        // a[m]=cinv*hyper_typ, b[n]=rinv*hypo_typ
__device__ float g_w_hypo[NN], g_w_hyper[NN];
__device__ float g_hpart[4 * HH], g_xpart[4 * HH];  // prototype partials

// ---------------- helpers ----------------
__device__ __forceinline__ float fast_tanh(float x) {
    float y;
    asm("tanh.approx.f32 %0, %1;" : "=f"(y) : "f"(x));
    return y;
}

__device__ __forceinline__ float block_sum128(float v, float* sh) {
    #pragma unroll
    for (int o = 16; o; o >>= 1) v += __shfl_xor_sync(0xffffffffu, v, o);
    int w = threadIdx.x >> 5;
    if ((threadIdx.x & 31) == 0) sh[w] = v;
    __syncthreads();
    return (sh[0] + sh[1]) + (sh[2] + sh[3]);
}

// ---------------- K1: E[n,m] = exp(invsqrt * sum_h tanh(X[n,h]*Y[m,h])) ----
// 32x32 tile per block, 16x16 threads, 2x2 micro-tile. MUFU-bound.
// Also writes the transposed tile to g_ET (smem-staged, coalesced).
__global__ __launch_bounds__(256) void att_kernel(const float* __restrict__ X,
                                                  const float* __restrict__ Y) {
    __shared__ float sX[32][33];
    __shared__ float sY[32][33];
    const int tid = threadIdx.x;
    const int tx = tid & 15;
    const int ty = tid >> 4;
    const int bi = blockIdx.y * 32;  // hypo rows
    const int bj = blockIdx.x * 32;  // hyper rows
    const int lr = tid >> 3;         // 0..31 load row
    const int lk = (tid & 7) << 2;   // 0..28 load k offset

    float a00 = 0.f, a01 = 0.f, a10 = 0.f, a11 = 0.f;

    for (int k0 = 0; k0 < HH; k0 += 32) {
        float4 vx = *(const float4*)(X + (size_t)(bi + lr) * HH + k0 + lk);
        float4 vy = *(const float4*)(Y + (size_t)(bj + lr) * HH + k0 + lk);
        sX[lr][lk + 0] = vx.x; sX[lr][lk + 1] = vx.y;
        sX[lr][lk + 2] = vx.z; sX[lr][lk + 3] = vx.w;
        sY[lr][lk + 0] = vy.x; sY[lr][lk + 1] = vy.y;
        sY[lr][lk + 2] = vy.z; sY[lr][lk + 3] = vy.w;
        __syncthreads();
        #pragma unroll
        for (int k = 0; k < 32; k++) {
            float x0 = sX[2 * ty][k], x1 = sX[2 * ty + 1][k];
            float y0 = sY[2 * tx][k], y1 = sY[2 * tx + 1][k];
            a00 += fast_tanh(x0 * y0);
            a01 += fast_tanh(x0 * y1);
            a10 += fast_tanh(x1 * y0);
            a11 += fast_tanh(x1 * y1);
        }
        __syncthreads();
    }

    // fused exp (softmax without max-shift: |att| <= 27.7, exp <= 1.1e12, safe)
    const float e00 = __expf(a00 * INV_SQRT_H);
    const float e01 = __expf(a01 * INV_SQRT_H);
    const float e10 = __expf(a10 * INV_SQRT_H);
    const float e11 = __expf(a11 * INV_SQRT_H);

    const int i = bi + 2 * ty, j = bj + 2 * tx;
    g_E[i * NN + j]           = e00;
    g_E[i * NN + j + 1]       = e01;
    g_E[(i + 1) * NN + j]     = e10;
    g_E[(i + 1) * NN + j + 1] = e11;

    // transposed tile via smem, then coalesced float4 store
    __syncthreads();
    sX[2 * tx][2 * ty]         = e00;
    sX[2 * tx + 1][2 * ty]     = e01;
    sX[2 * tx][2 * ty + 1]     = e10;
    sX[2 * tx + 1][2 * ty + 1] = e11;
    __syncthreads();
    float4 vt = make_float4(sX[lr][lk], sX[lr][lk + 1], sX[lr][lk + 2], sX[lr][lk + 3]);
    *(float4*)(g_ET + (size_t)(bj + lr) * NN + bi + lk) = vt;
}

// ---------------- K2: inverse row/col sums of E (all coalesced) ------------
__global__ __launch_bounds__(128) void sum_kernel() {
    __shared__ float sh[4];
    const int b = blockIdx.x, t = threadIdx.x;
    const float* row = (b < NN) ? (g_E + b * NN) : (g_ET + (b - NN) * NN);
    float s = row[t] + row[t + 128] + row[t + 256];
    s = block_sum128(s, sh);
    if (t == 0) {
        float inv = 1.0f / s;
        if (b < NN) g_rinv[b] = inv;
        else        g_cinv[b - NN] = inv;
    }
}

// ---------------- K3: typicalness vectors (pre-scaled) ----------------------
// b[n] = rinv[n] * hypo_typ[n],  hypo_typ[n]  = (1/384) sum_m E[n,m]*cinv[m]
// a[m] = cinv[m] * hyper_typ[m], hyper_typ[m] = (1/384) sum_n ET[m,n]*rinv[n]
__global__ __launch_bounds__(128) void typ_kernel() {
    __shared__ float sh[4];
    const int b = blockIdx.x, t = threadIdx.x;
    float acc = 0.f;
    if (b < NN) {
        const float* row = g_E + b * NN;
        #pragma unroll
        for (int i = 0; i < 3; i++) {
            int m = t + i * 128;
            acc += row[m] * g_cinv[m];
        }
        acc = block_sum128(acc, sh);
        if (t == 0) g_b[b] = acc * g_rinv[b] * INV_N;
    } else {
        const int c = b - NN;
        const float* row = g_ET + c * NN;
        #pragma unroll
        for (int i = 0; i < 3; i++) {
            int n = t + i * 128;
            acc += row[n] * g_rinv[n];
        }
        acc = block_sum128(acc, sh);
        if (t == 0) g_a[c] = acc * g_cinv[c] * INV_N;
    }
}

// ---------------- K4: pooling weights = two coalesced matvecs ---------------
// w_hypo[n]  = sum_m E[n,m]  * a[m]
// w_hyper[m] = sum_n ET[m,n] * b[n]
__global__ __launch_bounds__(128) void wvec_kernel() {
    __shared__ float sh[4];
    const int b = blockIdx.x, t = threadIdx.x;
    float acc = 0.f;
    if (b < NN) {
        const float* row = g_E + b * NN;
        #pragma unroll
        for (int i = 0; i < 3; i++) {
            int m = t + i * 128;
            acc += row[m] * g_a[m];
        }
        acc = block_sum128(acc, sh);
        if (t == 0) g_w_hypo[b] = acc;
    } else {
        const int c = b - NN;
        const float* row = g_ET + c * NN;
        #pragma unroll
        for (int i = 0; i < 3; i++) {
            int n = t + i * 128;
            acc += row[n] * g_b[n];
        }
        acc = block_sum128(acc, sh);
        if (t == 0) g_w_hyper[c] = acc;
    }
}

// ---------------- K5: prototype partials (24 blocks) ------------------------
// hp[d] = sum_m w_hyper[m]*Y[m,d];  xp[d] = sum_n w_hypo[n]*X[n,d]
__global__ __launch_bounds__(128) void proto_kernel(const float* __restrict__ X,
                                                    const float* __restrict__ Y) {
    __shared__ float wh[96];
    __shared__ float wx[96];
    const int t = threadIdx.x;
    const int m0 = blockIdx.y * 96;
    if (t < 96) {
        wh[t] = g_w_hyper[m0 + t];
        wx[t] = g_w_hypo[m0 + t];
    }
    __syncthreads();
    const int d = blockIdx.x * 128 + t;
    float hp = 0.f, xp = 0.f;
    #pragma unroll 8
    for (int m = 0; m < 96; m++) {
        hp += wh[m] * Y[(size_t)(m0 + m) * HH + d];
        xp += wx[m] * X[(size_t)(m0 + m) * HH + d];
    }
    g_hpart[blockIdx.y * HH + d] = hp;
    g_xpart[blockIdx.y * HH + d] = xp;
}

// ---------------- K6: combine partials + feats + classifier -----------------
__global__ __launch_bounds__(256) void cls_kernel(const float* __restrict__ W,
                                                  const float* __restrict__ B,
                                                  float* __restrict__ out) {
    __shared__ float sh[24];
    const int t = threadIdx.x;
    float p0 = 0.f, p1 = 0.f, p2 = 0.f;
    #pragma unroll
    for (int d = t; d < HH; d += 256) {
        float hp = g_hpart[d] + g_hpart[HH + d] + g_hpart[2 * HH + d] + g_hpart[3 * HH + d];
        float xp = g_xpart[d] + g_xpart[HH + d] + g_xpart[2 * HH + d] + g_xpart[3 * HH + d];
        float fd = hp - xp;
        float fm = hp * xp;
        p0 += W[d] * hp + W[HH + d] * xp + W[2 * HH + d] * fd + W[3 * HH + d] * fm;
        p1 += W[4 * HH + d] * hp + W[5 * HH + d] * xp + W[6 * HH + d] * fd + W[7 * HH + d] * fm;
        p2 += W[8 * HH + d] * hp + W[9 * HH + d] * xp + W[10 * HH + d] * fd + W[11 * HH + d] * fm;
    }
    #pragma unroll
    for (int o = 16; o; o >>= 1) {
        p0 += __shfl_xor_sync(0xffffffffu, p0, o);
        p1 += __shfl_xor_sync(0xffffffffu, p1, o);
        p2 += __shfl_xor_sync(0xffffffffu, p2, o);
    }
    int w = t >> 5;
    if ((t & 31) == 0) { sh[w] = p0; sh[8 + w] = p1; sh[16 + w] = p2; }
    __syncthreads();
    if (t == 0) {
        float s0 = 0.f, s1 = 0.f, s2 = 0.f;
        #pragma unroll
        for (int i = 0; i < 8; i++) { s0 += sh[i]; s1 += sh[8 + i]; s2 += sh[16 + i]; }
        out[0] = s0 + B[0];
        out[1] = s1 + B[1];
        out[2] = s2 + B[2];
    }
}

// ---------------- launch ------------------------------------------------------
extern "C" void kernel_launch(void* const* d_in, const int* in_sizes, int n_in,
                              void* d_out, int out_size) {
    const float* X = (const float*)d_in[0];  // hypo_embeddings [384,768]
    const float* Y = (const float*)d_in[1];  // hyper_embeddings [384,768]
    const float* W = (const float*)d_in[2];  // W_cls [3,3072]
    const float* B = (const float*)d_in[3];  // b_cls [3]
    float* out = (float*)d_out;              // [3]

    att_kernel<<<dim3(12, 12), 256>>>(X, Y);
    sum_kernel<<<2 * NN, 128>>>();
    typ_kernel<<<2 * NN, 128>>>();
    wvec_kernel<<<2 * NN, 128>>>();
    proto_kernel<<<dim3(6, 4), 128>>>(X, Y);
    cls_kernel<<<1, 256>>>(W, B, out);
}